// round 12
// baseline (speedup 1.0000x reference)
#include <cuda_runtime.h>
#include <cuda_bf16.h>

// MQCNN layer, closed form (R0 derivation):
// Wires 0-3 get H -> uniform superposition over 16 control branches; the 12
// controlled-RY on wire 4 compose additively per branch; H + 24 controlled-U3
// act only on wires 5,6 and preserve the wire-4 marginal (U3_w is dead).
// <Z>_4 = (1/16) sum_b cos(theta_b) = 11 distinct cosines:
// z = (6cos(a) + cos(a+s1)+cos(a+s2)+cos(a+s3)+cos(a+s4)+cos(a+s5)
//    + cos(a+s1+s3)+cos(a+s2+s5)+cos(a+s2+s3+s4)+cos(a+s1+s4+s5)
//    + cos(a+s1+s2+s3+s4+s5)) / 16
//
// Body == R6/R8 terminal optimum (kernel 5.02-5.31us over four runs; floor =
// one latency-limited 6.8MB DRAM pass + launch ramp, all pipes <=16%,
// design space R0-R10 fully scanned and flat). R11 change: streaming cache
// policy only — __ldcs on the 6 single-use input loads, __stcs on the
// never-re-read output store. Same instruction count/registers/schedule.

#define CH_STRIDE (128 * 128)
#define N_OUT (32 * 64 * 64)

__global__ __launch_bounds__(256) void mqcnn_kernel(
    const float* __restrict__ x, float* __restrict__ out)
{
    int tid = blockIdx.x * blockDim.x + threadIdx.x;

    int k = tid & 63;
    int j = (tid >> 6) & 63;
    int b = tid >> 12;

    // x[b, 0, 2j, 2k]
    const float* base = x + (size_t)b * (3 * CH_STRIDE)
                          + (size_t)j * 256 + 2 * k;

    float2 c0r0 = __ldcs(reinterpret_cast<const float2*>(base));
    float2 c0r1 = __ldcs(reinterpret_cast<const float2*>(base + 128));
    float2 c1r0 = __ldcs(reinterpret_cast<const float2*>(base + CH_STRIDE));
    float2 c1r1 = __ldcs(reinterpret_cast<const float2*>(base + CH_STRIDE + 128));
    float2 c2r0 = __ldcs(reinterpret_cast<const float2*>(base + 2 * CH_STRIDE));
    float2 c2r1 = __ldcs(reinterpret_cast<const float2*>(base + 2 * CH_STRIDE + 128));

    float a  = c0r0.x + c1r0.x + c2r0.x;
    float s1 = c0r0.y + c1r1.x;
    float s2 = c0r1.x + c2r1.y;
    float s3 = c0r1.y;
    float s4 = c1r0.y + c2r1.x;
    float s5 = c1r1.y + c2r0.y;

    float a1  = a + s1;
    float a2  = a + s2;
    float s45 = s4 + s5;

    float sum = 6.0f * __cosf(a);
    sum += __cosf(a1);
    sum += __cosf(a2);
    sum += __cosf(a + s3);
    sum += __cosf(a + s4);
    sum += __cosf(a + s5);
    sum += __cosf(a1 + s3);             // a+s1+s3
    sum += __cosf(a2 + s5);             // a+s2+s5
    sum += __cosf(a2 + s3 + s4);        // a+s2+s3+s4
    sum += __cosf(a1 + s45);            // a+s1+s4+s5
    sum += __cosf(a1 + s2 + s3 + s45);  // a+all

    __stcs(out + tid, sum * 0.0625f);
}

extern "C" void kernel_launch(void* const* d_in, const int* in_sizes, int n_in,
                              void* d_out, int out_size) {
    const float* x = (const float*)d_in[0];   // [32,3,128,128] float32
    float* out = (float*)d_out;               // [32,1,64,64] float32
    mqcnn_kernel<<<N_OUT / 256, 256>>>(x, out);
}

// round 13
// speedup vs baseline: 1.0142x; 1.0142x over previous
#include <cuda_runtime.h>
#include <cuda_bf16.h>

// MQCNN layer, closed form (R0 derivation):
// Wires 0-3 get H -> uniform superposition over 16 control branches; the 12
// controlled-RY on wire 4 compose additively per branch; H + 24 controlled-U3
// act only on wires 5,6 and preserve the wire-4 marginal (U3_w is dead).
// <Z>_4 = (1/16) sum_b cos(theta_b) = 11 distinct cosines:
// z = (6cos(a) + cos(a+s1)+cos(a+s2)+cos(a+s3)+cos(a+s4)+cos(a+s5)
//    + cos(a+s1+s3)+cos(a+s2+s5)+cos(a+s2+s3+s4)+cos(a+s1+s4+s5)
//    + cos(a+s1+s2+s3+s4+s5)) / 16
//
// FINAL == R6/R8 measured optimum. 13-run ledger: occ 13-71% flat above
// 21%; MLP 3-12 flat; block {128:5.41, 256:5.02, 512:5.47}; 2x instr-count
// flat; serial==tree==shfl-split; streaming (.cs) cache policy worse than
// default (5.47 vs 5.02-5.31, and it discards warm-L2 residency the timed
// graph replays benefit from). Floor = one latency-limited 6.8MB DRAM pass
// (~1.25TB/s) + ~2.5us launch ramp; all pipes <=16%; traffic and MUFU
// count both information-minimal. Shape: grid 512 x block 256, 1 output/
// thread, 6x coalesced LDG.64, exact-cover grid, CSE'd arguments.

#define CH_STRIDE (128 * 128)
#define N_OUT (32 * 64 * 64)

__global__ __launch_bounds__(256) void mqcnn_kernel(
    const float* __restrict__ x, float* __restrict__ out)
{
    int tid = blockIdx.x * blockDim.x + threadIdx.x;

    int k = tid & 63;
    int j = (tid >> 6) & 63;
    int b = tid >> 12;

    // x[b, 0, 2j, 2k]
    const float* base = x + (size_t)b * (3 * CH_STRIDE)
                          + (size_t)j * 256 + 2 * k;

    float2 c0r0 = *reinterpret_cast<const float2*>(base);
    float2 c0r1 = *reinterpret_cast<const float2*>(base + 128);
    float2 c1r0 = *reinterpret_cast<const float2*>(base + CH_STRIDE);
    float2 c1r1 = *reinterpret_cast<const float2*>(base + CH_STRIDE + 128);
    float2 c2r0 = *reinterpret_cast<const float2*>(base + 2 * CH_STRIDE);
    float2 c2r1 = *reinterpret_cast<const float2*>(base + 2 * CH_STRIDE + 128);

    float a  = c0r0.x + c1r0.x + c2r0.x;
    float s1 = c0r0.y + c1r1.x;
    float s2 = c0r1.x + c2r1.y;
    float s3 = c0r1.y;
    float s4 = c1r0.y + c2r1.x;
    float s5 = c1r1.y + c2r0.y;

    float a1  = a + s1;
    float a2  = a + s2;
    float s45 = s4 + s5;

    float sum = 6.0f * __cosf(a);
    sum += __cosf(a1);
    sum += __cosf(a2);
    sum += __cosf(a + s3);
    sum += __cosf(a + s4);
    sum += __cosf(a + s5);
    sum += __cosf(a1 + s3);             // a+s1+s3
    sum += __cosf(a2 + s5);             // a+s2+s5
    sum += __cosf(a2 + s3 + s4);        // a+s2+s3+s4
    sum += __cosf(a1 + s45);            // a+s1+s4+s5
    sum += __cosf(a1 + s2 + s3 + s45);  // a+all

    out[tid] = sum * 0.0625f;
}

extern "C" void kernel_launch(void* const* d_in, const int* in_sizes, int n_in,
                              void* d_out, int out_size) {
    const float* x = (const float*)d_in[0];   // [32,3,128,128] float32
    float* out = (float*)d_out;               // [32,1,64,64] float32
    mqcnn_kernel<<<N_OUT / 256, 256>>>(x, out);
}

// round 14
// speedup vs baseline: 1.0337x; 1.0192x over previous
#include <cuda_runtime.h>
#include <cuda_bf16.h>

// MQCNN layer, closed form (R0 derivation):
// Wires 0-3 get H -> uniform superposition over 16 control branches; the 12
// controlled-RY on wire 4 compose additively per branch; H + 24 controlled-U3
// act only on wires 5,6 and preserve the wire-4 marginal (U3_w is dead).
// <Z>_4 = (1/16) sum_b cos(theta_b) = 11 distinct cosines:
// z = (6cos(a) + cos(a+s1)+cos(a+s2)+cos(a+s3)+cos(a+s4)+cos(a+s5)
//    + cos(a+s1+s3)+cos(a+s2+s5)+cos(a+s2+s3+s4)+cos(a+s1+s4+s5)
//    + cos(a+s1+s2+s3+s4+s5)) / 16
//
// TERMINAL FIXED POINT (14 runs). Kernel band 5.02-5.47us on this exact
// binary (pure jitter); every design axis scanned: occ 13-71% flat above
// 21%, MLP 3-12 flat, block {128:5.41, 256:5.02, 512:5.47}, 2x instr-count
// flat, serial==tree==shfl-split reduction, streaming cache policy worse
// than default. Floor = one latency-limited 6.8MB DRAM pass + ~5k-cycle
// launch overhead (T_ovh, content-independent); all pipes <=16%; traffic
// and MUFU count information-minimal. Harness dur = kernel + 1.3-1.9us
// replay overhead, uncorrelated with kernel content. Shape: grid 512 x
// block 256, 1 output/thread, 6x coalesced LDG.64, exact-cover grid.

#define CH_STRIDE (128 * 128)
#define N_OUT (32 * 64 * 64)

__global__ __launch_bounds__(256) void mqcnn_kernel(
    const float* __restrict__ x, float* __restrict__ out)
{
    int tid = blockIdx.x * blockDim.x + threadIdx.x;

    int k = tid & 63;
    int j = (tid >> 6) & 63;
    int b = tid >> 12;

    // x[b, 0, 2j, 2k]
    const float* base = x + (size_t)b * (3 * CH_STRIDE)
                          + (size_t)j * 256 + 2 * k;

    float2 c0r0 = *reinterpret_cast<const float2*>(base);
    float2 c0r1 = *reinterpret_cast<const float2*>(base + 128);
    float2 c1r0 = *reinterpret_cast<const float2*>(base + CH_STRIDE);
    float2 c1r1 = *reinterpret_cast<const float2*>(base + CH_STRIDE + 128);
    float2 c2r0 = *reinterpret_cast<const float2*>(base + 2 * CH_STRIDE);
    float2 c2r1 = *reinterpret_cast<const float2*>(base + 2 * CH_STRIDE + 128);

    float a  = c0r0.x + c1r0.x + c2r0.x;
    float s1 = c0r0.y + c1r1.x;
    float s2 = c0r1.x + c2r1.y;
    float s3 = c0r1.y;
    float s4 = c1r0.y + c2r1.x;
    float s5 = c1r1.y + c2r0.y;

    float a1  = a + s1;
    float a2  = a + s2;
    float s45 = s4 + s5;

    float sum = 6.0f * __cosf(a);
    sum += __cosf(a1);
    sum += __cosf(a2);
    sum += __cosf(a + s3);
    sum += __cosf(a + s4);
    sum += __cosf(a + s5);
    sum += __cosf(a1 + s3);             // a+s1+s3
    sum += __cosf(a2 + s5);             // a+s2+s5
    sum += __cosf(a2 + s3 + s4);        // a+s2+s3+s4
    sum += __cosf(a1 + s45);            // a+s1+s4+s5
    sum += __cosf(a1 + s2 + s3 + s45);  // a+all

    out[tid] = sum * 0.0625f;
}

extern "C" void kernel_launch(void* const* d_in, const int* in_sizes, int n_in,
                              void* d_out, int out_size) {
    const float* x = (const float*)d_in[0];   // [32,3,128,128] float32
    float* out = (float*)d_out;               // [32,1,64,64] float32
    mqcnn_kernel<<<N_OUT / 256, 256>>>(x, out);
}